// round 3
// baseline (speedup 1.0000x reference)
#include <cuda_runtime.h>

#define B_   16
#define C_   512
#define N_   1024
#define CI_  256
#define EPS_ 1e-5f

// ---------------- scratch (static device globals; no allocs allowed) ----------------
__device__ float g_re[(size_t)B_ * CI_ * N_];          // 16 MB  rgb embed  [b][ci][n]
__device__ float g_fe[(size_t)B_ * CI_ * N_];          // 16 MB  flow embed
__device__ float g_sc[(size_t)B_ * N_ * N_];           // 64 MB  scores -> P1 (in place)
__device__ float g_p2[(size_t)B_ * N_ * N_];           // 64 MB  P2
__device__ float g_yr[(size_t)B_ * CI_ * N_];          // 16 MB  rgb_y
__device__ float g_yf[(size_t)B_ * CI_ * N_];          // 16 MB  flow_y
__device__ float g_rmax[B_ * N_], g_rsum[B_ * N_];     // row softmax stats (rsum stores 1/sum)
__device__ float g_cmax[B_ * N_], g_csum[B_ * N_];     // col softmax stats (csum stores 1/sum)
__device__ float g_mean[2 * C_], g_rstd[2 * C_];       // BN stats

// ---------------- generic tiled SGEMM ----------------
// C[m,n] = sum_k A(m,k) * B(k,n)  (+ bias[m])
// LA==0: A is [M,K] row-major (A[m*lda+k]);  LA==1: A is [K,M] (A[k*lda+m])
// LB==0: B is [K,N] row-major (B[k*ldb+n]);  LB==1: B is [N,K] (B[n*ldb+k])
// Requires M%128==0, N%128==0, K%16==0 (true for every call here).
template<int LA, int LB, bool BIAS>
__global__ __launch_bounds__(256, 2)
void gemm_kernel(const float* __restrict__ A, const float* __restrict__ B,
                 float* __restrict__ C, const float* __restrict__ bias,
                 int M, int N, int K, int lda, int ldb, int ldc,
                 long long sA, long long sB, long long sC)
{
    constexpr int BM = 128, BN = 128, BK = 16;
    __shared__ float As[BK][BM + 4];
    __shared__ float Bs[BK][BN + 4];

    A += (long long)blockIdx.z * sA;
    B += (long long)blockIdx.z * sB;
    C += (long long)blockIdx.z * sC;

    const int m0 = blockIdx.y * BM;
    const int n0 = blockIdx.x * BN;
    const int tid = threadIdx.x;
    const int tx = tid & 15, ty = tid >> 4;

    float acc[8][8];
#pragma unroll
    for (int i = 0; i < 8; i++)
#pragma unroll
        for (int j = 0; j < 8; j++) acc[i][j] = 0.f;

    float4 rA[2], rB[2];

    auto gloadA = [&](int k0) {
#pragma unroll
        for (int i = 0; i < 2; i++) {
            int f = tid + i * 256;
            if constexpr (LA == 0) {
                int row = f >> 2, cv = f & 3;
                rA[i] = *(const float4*)(A + (long long)(m0 + row) * lda + (k0 + cv * 4));
            } else {
                int k = f >> 5, mv = (f & 31) << 2;
                rA[i] = *(const float4*)(A + (long long)(k0 + k) * lda + (m0 + mv));
            }
        }
    };
    auto gloadB = [&](int k0) {
#pragma unroll
        for (int i = 0; i < 2; i++) {
            int f = tid + i * 256;
            if constexpr (LB == 0) {
                int k = f >> 5, nv = (f & 31) << 2;
                rB[i] = *(const float4*)(B + (long long)(k0 + k) * ldb + (n0 + nv));
            } else {
                int row = f >> 2, cv = f & 3;
                rB[i] = *(const float4*)(B + (long long)(n0 + row) * ldb + (k0 + cv * 4));
            }
        }
    };
    auto sstoreA = [&]() {
#pragma unroll
        for (int i = 0; i < 2; i++) {
            int f = tid + i * 256;
            if constexpr (LA == 0) {
                int row = f >> 2, cv = (f & 3) << 2;
                As[cv + 0][row] = rA[i].x; As[cv + 1][row] = rA[i].y;
                As[cv + 2][row] = rA[i].z; As[cv + 3][row] = rA[i].w;
            } else {
                int k = f >> 5, mv = (f & 31) << 2;
                *(float4*)&As[k][mv] = rA[i];
            }
        }
    };
    auto sstoreB = [&]() {
#pragma unroll
        for (int i = 0; i < 2; i++) {
            int f = tid + i * 256;
            if constexpr (LB == 0) {
                int k = f >> 5, nv = (f & 31) << 2;
                *(float4*)&Bs[k][nv] = rB[i];
            } else {
                int row = f >> 2, cv = (f & 3) << 2;
                Bs[cv + 0][row] = rB[i].x; Bs[cv + 1][row] = rB[i].y;
                Bs[cv + 2][row] = rB[i].z; Bs[cv + 3][row] = rB[i].w;
            }
        }
    };

    gloadA(0); gloadB(0);
    sstoreA(); sstoreB();
    __syncthreads();

    const int ktiles = K >> 4;
    for (int kt = 0; kt < ktiles; kt++) {
        if (kt + 1 < ktiles) { gloadA((kt + 1) << 4); gloadB((kt + 1) << 4); }
#pragma unroll
        for (int kk = 0; kk < BK; kk++) {
            float4 a0 = *(const float4*)&As[kk][ty * 8];
            float4 a1 = *(const float4*)&As[kk][ty * 8 + 4];
            float4 b0 = *(const float4*)&Bs[kk][tx * 8];
            float4 b1 = *(const float4*)&Bs[kk][tx * 8 + 4];
            float a[8] = {a0.x, a0.y, a0.z, a0.w, a1.x, a1.y, a1.z, a1.w};
            float bb[8] = {b0.x, b0.y, b0.z, b0.w, b1.x, b1.y, b1.z, b1.w};
#pragma unroll
            for (int i = 0; i < 8; i++)
#pragma unroll
                for (int j = 0; j < 8; j++) acc[i][j] += a[i] * bb[j];
        }
        __syncthreads();
        if (kt + 1 < ktiles) { sstoreA(); sstoreB(); __syncthreads(); }
    }

#pragma unroll
    for (int i = 0; i < 8; i++) {
        int m = m0 + ty * 8 + i;
        float bv = 0.f;
        if constexpr (BIAS) bv = bias[m];
        float4 o0 = make_float4(acc[i][0] + bv, acc[i][1] + bv, acc[i][2] + bv, acc[i][3] + bv);
        float4 o1 = make_float4(acc[i][4] + bv, acc[i][5] + bv, acc[i][6] + bv, acc[i][7] + bv);
        *(float4*)(C + (long long)m * ldc + n0 + tx * 8)     = o0;
        *(float4*)(C + (long long)m * ldc + n0 + tx * 8 + 4) = o1;
    }
}

// ---------------- softmax stats ----------------
// Row stats: one block per (b, n); online max/sum over m (contiguous row).
__global__ void row_stats_kernel()
{
    long long row = blockIdx.x;                    // b*N + n
    const float* s = g_sc + (row << 10);
    int tid = threadIdx.x;
    float mx = -1e30f, sum = 0.f;
    for (int i = tid; i < N_; i += 256) {
        float x = s[i];
        if (x > mx) { sum = sum * __expf(mx - x) + 1.f; mx = x; }
        else        { sum += __expf(x - mx); }
    }
    __shared__ float sm[256], ss[256];
    sm[tid] = mx; ss[tid] = sum;
    __syncthreads();
    for (int o = 128; o > 0; o >>= 1) {
        if (tid < o) {
            float m2 = sm[tid + o], s2 = ss[tid + o];
            float M = fmaxf(sm[tid], m2);
            ss[tid] = ss[tid] * __expf(sm[tid] - M) + s2 * __expf(m2 - M);
            sm[tid] = M;
        }
        __syncthreads();
    }
    if (tid == 0) { g_rmax[row] = sm[0]; g_rsum[row] = 1.f / ss[0]; }
}

// Col stats: one thread per (b, m); loop over n (coalesced across threads).
__global__ void col_stats_kernel()
{
    int col = blockIdx.x * blockDim.x + threadIdx.x;  // b*N + m
    int b = col >> 10, m = col & (N_ - 1);
    const float* s = g_sc + ((long long)b << 20) + m;
    float mx = -1e30f, sum = 0.f;
#pragma unroll 4
    for (int n = 0; n < N_; n++) {
        float x = s[(long long)n << 10];
        if (x > mx) { sum = sum * __expf(mx - x) + 1.f; mx = x; }
        else        { sum += __expf(x - mx); }
    }
    g_cmax[col] = mx;
    g_csum[col] = 1.f / sum;
}

// P-write: read scores once; write P1 (row softmax) in place, P2 (col softmax) to g_p2.
__global__ void p_write_kernel()
{
    const long long total4 = ((long long)B_ << 20) >> 2;   // 4M float4
    const long long stride = (long long)gridDim.x * blockDim.x;
    for (long long i = (long long)blockIdx.x * blockDim.x + threadIdx.x; i < total4; i += stride) {
        long long e  = i << 2;
        long long bn = e >> 10;                 // b*N + n
        int       m  = (int)(e & (N_ - 1));
        int   cbase  = (int)((e >> 20) << 10) + m;   // b*N + m
        float4 s = *((const float4*)g_sc + i);
        float rm = g_rmax[bn], ri = g_rsum[bn];
        float4 p2;
        p2.x = __expf(s.x - g_cmax[cbase + 0]) * g_csum[cbase + 0];
        p2.y = __expf(s.y - g_cmax[cbase + 1]) * g_csum[cbase + 1];
        p2.z = __expf(s.z - g_cmax[cbase + 2]) * g_csum[cbase + 2];
        p2.w = __expf(s.w - g_cmax[cbase + 3]) * g_csum[cbase + 3];
        *((float4*)g_p2 + i) = p2;
        float4 p1;
        p1.x = __expf(s.x - rm) * ri;
        p1.y = __expf(s.y - rm) * ri;
        p1.z = __expf(s.z - rm) * ri;
        p1.w = __expf(s.w - rm) * ri;
        *((float4*)g_sc + i) = p1;
    }
}

// ---------------- batchnorm ----------------
// One block per channel (2 streams * 512 ch). z already lives in d_out.
__global__ void bn_stats_kernel(const float* __restrict__ z)
{
    int ch = blockIdx.x;                 // 0..1023
    int s = ch >> 9, c = ch & (C_ - 1);
    const float* base = z + ((long long)s * B_ * C_ + c) * N_;
    float sum = 0.f, sq = 0.f;
    for (int i = threadIdx.x; i < B_ * N_; i += 256) {
        int b = i >> 10, n = i & (N_ - 1);
        float x = base[((long long)b * C_) * (long long)N_ + n];
        sum += x; sq += x * x;
    }
    __shared__ float ssum[256], ssq[256];
    int tid = threadIdx.x;
    ssum[tid] = sum; ssq[tid] = sq;
    __syncthreads();
    for (int o = 128; o > 0; o >>= 1) {
        if (tid < o) { ssum[tid] += ssum[tid + o]; ssq[tid] += ssq[tid + o]; }
        __syncthreads();
    }
    if (tid == 0) {
        const float inv = 1.f / (float)(B_ * N_);
        float mean = ssum[0] * inv;
        float var  = ssq[0] * inv - mean * mean;
        g_mean[ch] = mean;
        g_rstd[ch] = rsqrtf(var + EPS_);
    }
}

// Normalize in place + gamma/beta + residual add.
__global__ void finalize_kernel(float* __restrict__ out,
                                const float* __restrict__ rgb, const float* __restrict__ flow,
                                const float* __restrict__ gr,  const float* __restrict__ br,
                                const float* __restrict__ gf,  const float* __restrict__ bf)
{
    const long long half4  = ((long long)B_ * C_ * N_) >> 2;   // per stream
    const long long total4 = half4 * 2;
    const long long stride = (long long)gridDim.x * blockDim.x;
    for (long long i = (long long)blockIdx.x * blockDim.x + threadIdx.x; i < total4; i += stride) {
        int s = (i >= half4);
        long long r4 = i - (long long)s * half4;
        long long e  = r4 << 2;
        int c = (int)((e >> 10) & (C_ - 1));
        float mean = g_mean[(s << 9) + c];
        float a    = g_rstd[(s << 9) + c] * (s ? gf[c] : gr[c]);
        float be   = (s ? bf[c] : br[c]);
        float4 res = *((const float4*)(s ? flow : rgb) + r4);
        float4 z   = *((float4*)out + i);
        z.x = (z.x - mean) * a + be + res.x;
        z.y = (z.y - mean) * a + be + res.y;
        z.z = (z.z - mean) * a + be + res.z;
        z.w = (z.w - mean) * a + be + res.w;
        *((float4*)out + i) = z;
    }
}

// ---------------- launcher ----------------
extern "C" void kernel_launch(void* const* d_in, const int* in_sizes, int n_in,
                              void* d_out, int out_size)
{
    const float* rgb        = (const float*)d_in[0];
    const float* flow       = (const float*)d_in[1];
    const float* wg_rgb     = (const float*)d_in[2];
    const float* bg_rgb     = (const float*)d_in[3];
    const float* wg_flow    = (const float*)d_in[4];
    const float* bg_flow    = (const float*)d_in[5];
    const float* ww_rgb     = (const float*)d_in[6];
    const float* bw_rgb     = (const float*)d_in[7];
    const float* gamma_rgb  = (const float*)d_in[8];
    const float* beta_rgb   = (const float*)d_in[9];
    const float* ww_flow    = (const float*)d_in[10];
    const float* bw_flow    = (const float*)d_in[11];
    const float* gamma_flow = (const float*)d_in[12];
    const float* beta_flow  = (const float*)d_in[13];
    float* out = (float*)d_out;

    // Resolve scratch symbol addresses once (first call is the un-captured
    // correctness run; subsequent captured calls reuse cached pointers).
    static float *re = nullptr, *fe, *sc, *p2, *yr, *yf;
    if (!re) {
        cudaGetSymbolAddress((void**)&re, g_re);
        cudaGetSymbolAddress((void**)&fe, g_fe);
        cudaGetSymbolAddress((void**)&sc, g_sc);
        cudaGetSymbolAddress((void**)&p2, g_p2);
        cudaGetSymbolAddress((void**)&yr, g_yr);
        cudaGetSymbolAddress((void**)&yf, g_yf);
    }

    const long long sEmb = (long long)CI_ * N_;    // 256*1024
    const long long sIn  = (long long)C_  * N_;    // 512*1024
    const long long sSc  = (long long)N_  * N_;    // 1024*1024
    dim3 blk(256);

    // 1) embeddings: re = wg_rgb @ rgb + bg ; fe = wg_flow @ flow + bg
    gemm_kernel<0, 0, true><<<dim3(8, 2, B_), blk>>>(wg_rgb, rgb, re, bg_rgb,
        CI_, N_, C_, C_, N_, N_, 0, sIn, sEmb);
    gemm_kernel<0, 0, true><<<dim3(8, 2, B_), blk>>>(wg_flow, flow, fe, bg_flow,
        CI_, N_, C_, C_, N_, N_, 0, sIn, sEmb);

    // 2) scores[n,m] = sum_i re[i,n] * fe[i,m]   (TN)
    gemm_kernel<1, 0, false><<<dim3(8, 8, B_), blk>>>(re, fe, sc, nullptr,
        N_, N_, CI_, N_, N_, N_, sEmb, sEmb, sSc);

    // 3) softmax stats + probability write (P1 in place, P2 to g_p2)
    row_stats_kernel<<<B_ * N_, 256>>>();
    col_stats_kernel<<<(B_ * N_) / 128, 128>>>();
    p_write_kernel<<<1184, 256>>>();

    // 4) rgb_y = fe @ P1^T (NT) ; flow_y = re @ P2 (NN)
    gemm_kernel<0, 1, false><<<dim3(8, 2, B_), blk>>>(fe, sc, yr, nullptr,
        CI_, N_, N_, N_, N_, N_, sEmb, sSc, sEmb);
    gemm_kernel<0, 0, false><<<dim3(8, 2, B_), blk>>>(re, p2, yf, nullptr,
        CI_, N_, N_, N_, N_, N_, sEmb, sSc, sEmb);

    // 5) output convs (pre-BN z written straight into d_out)
    gemm_kernel<0, 0, true><<<dim3(8, 4, B_), blk>>>(ww_rgb, yr, out, bw_rgb,
        C_, N_, CI_, CI_, N_, N_, 0, sEmb, sIn);
    gemm_kernel<0, 0, true><<<dim3(8, 4, B_), blk>>>(ww_flow, yf, out + (long long)B_ * C_ * N_, bw_flow,
        C_, N_, CI_, CI_, N_, N_, 0, sEmb, sIn);

    // 6) BN stats + normalize + residual
    bn_stats_kernel<<<2 * C_, 256>>>(out);
    finalize_kernel<<<1184, 256>>>(out, rgb, flow, gamma_rgb, beta_rgb, gamma_flow, beta_flow);
}

// round 4
// speedup vs baseline: 2.5721x; 2.5721x over previous
#include <cuda_runtime.h>

#define B_   16
#define C_   512
#define N_   1024
#define CI_  256
#define EPS_ 1e-5f

// ---------------- scratch (static device globals; no allocs allowed) ----------------
__device__ float g_re[(size_t)B_ * CI_ * N_];          // 16 MB  rgb embed  [b][ci][n]
__device__ float g_fe[(size_t)B_ * CI_ * N_];          // 16 MB  flow embed
__device__ float g_sc[(size_t)B_ * N_ * N_];           // 64 MB  scores -> E=exp(scores) in place
__device__ float g_yr[(size_t)B_ * CI_ * N_];          // 16 MB  rgb_y
__device__ float g_yf[(size_t)B_ * CI_ * N_];          // 16 MB  flow_y
__device__ float g_rsum[B_ * N_];                      // 1/rowsum of E
__device__ float g_csum[B_ * N_];                      // 1/colsum of E
__device__ float g_mean[2 * C_], g_rstd[2 * C_];       // BN stats

// ---------------- helpers ----------------
__device__ __forceinline__ unsigned f2tf(float f) {
    unsigned u; asm("cvt.rna.tf32.f32 %0, %1;" : "=r"(u) : "f"(f)); return u;
}
__device__ __forceinline__ float4 cvt4(float4 v) {
    v.x = __uint_as_float(f2tf(v.x));
    v.y = __uint_as_float(f2tf(v.y));
    v.z = __uint_as_float(f2tf(v.z));
    v.w = __uint_as_float(f2tf(v.w));
    return v;
}
__device__ __forceinline__ void mma8(float* d, const unsigned* a, const unsigned* b) {
    asm volatile(
        "mma.sync.aligned.m16n8k8.row.col.f32.tf32.tf32.f32 "
        "{%0,%1,%2,%3}, {%4,%5,%6,%7}, {%8,%9}, {%0,%1,%2,%3};"
        : "+f"(d[0]), "+f"(d[1]), "+f"(d[2]), "+f"(d[3])
        : "r"(a[0]), "r"(a[1]), "r"(a[2]), "r"(a[3]), "r"(b[0]), "r"(b[1]));
}

// ---------------- tf32 tensor-core GEMM ----------------
// C[m,n] = sum_k A(m,k) * B(k,n)   (optionally + bias[m]  or  * colscale[n])
// LA==0: A is [M,K] row-major;  LA==1: A is [K,M] row-major
// LB==0: B is [K,N] row-major;  LB==1: B is [N,K] row-major
// EPI: 0=none, 1=bias per output row (aux[m]), 2=scale per output col (aux[n])
// Requires M%128==0, N%128==0, K%16==0.
// Block tile 128x128x16, 8 warps as 2(m) x 4(n), each warp 64x32 via m16n8k8.
template<int LA, int LB, int EPI>
__global__ __launch_bounds__(256, 2)
void mma_gemm(const float* __restrict__ A, const float* __restrict__ B,
              float* __restrict__ C, const float* __restrict__ aux,
              int M, int N, int K, int lda, int ldb, int ldc,
              long long sA, long long sB, long long sC, long long sAux)
{
    // layout strides (floats):
    //   row-major staging  : [row][k], stride 20  (conflict-free frag reads: 20g+t)
    //   k-major staging    : [k][row], stride 136 (conflict-free frag reads: 8t+g)
    __shared__ float smA[2560];   // max(128*20, 16*136)
    __shared__ float smB[2560];

    A += (long long)blockIdx.z * sA;
    B += (long long)blockIdx.z * sB;
    C += (long long)blockIdx.z * sC;
    const float* auxp = aux + (long long)blockIdx.z * sAux;

    const int m0 = blockIdx.y * 128;
    const int n0 = blockIdx.x * 128;
    const int tid  = threadIdx.x;
    const int wid  = tid >> 5, lane = tid & 31;
    const int wm   = wid & 1,  wn   = wid >> 1;     // 2 x 4 warps
    const int g    = lane >> 2, t   = lane & 3;

    float acc[4][4][4];
#pragma unroll
    for (int i = 0; i < 4; i++)
#pragma unroll
        for (int j = 0; j < 4; j++) {
            acc[i][j][0] = 0.f; acc[i][j][1] = 0.f;
            acc[i][j][2] = 0.f; acc[i][j][3] = 0.f;
        }

    float4 rA[2], rB[2];

    auto gload = [&](int k0) {
#pragma unroll
        for (int i = 0; i < 2; i++) {
            int f = tid + i * 256;
            if constexpr (LA == 0) {
                int row = f >> 2, cv = f & 3;
                rA[i] = *(const float4*)(A + (long long)(m0 + row) * lda + (k0 + cv * 4));
            } else {
                int k = f >> 5, mv = (f & 31) << 2;
                rA[i] = *(const float4*)(A + (long long)(k0 + k) * lda + (m0 + mv));
            }
            if constexpr (LB == 0) {
                int k = f >> 5, nv = (f & 31) << 2;
                rB[i] = *(const float4*)(B + (long long)(k0 + k) * ldb + (n0 + nv));
            } else {
                int row = f >> 2, cv = f & 3;
                rB[i] = *(const float4*)(B + (long long)(n0 + row) * ldb + (k0 + cv * 4));
            }
        }
    };
    auto sstore = [&]() {
#pragma unroll
        for (int i = 0; i < 2; i++) {
            int f = tid + i * 256;
            if constexpr (LA == 0) {
                int row = f >> 2, cv = f & 3;
                *(float4*)&smA[row * 20 + cv * 4] = cvt4(rA[i]);
            } else {
                int k = f >> 5, mv = (f & 31) << 2;
                *(float4*)&smA[k * 136 + mv] = cvt4(rA[i]);
            }
            if constexpr (LB == 0) {
                int k = f >> 5, nv = (f & 31) << 2;
                *(float4*)&smB[k * 136 + nv] = cvt4(rB[i]);
            } else {
                int row = f >> 2, cv = f & 3;
                *(float4*)&smB[row * 20 + cv * 4] = cvt4(rB[i]);
            }
        }
    };

    gload(0);
    sstore();
    __syncthreads();

    const unsigned* sa = (const unsigned*)smA;
    const unsigned* sb = (const unsigned*)smB;
    const int ktiles = K >> 4;

    for (int kt = 0; kt < ktiles; kt++) {
        if (kt + 1 < ktiles) gload((kt + 1) << 4);
#pragma unroll
        for (int ks = 0; ks < 16; ks += 8) {
            unsigned af[4][4], bf[4][2];
#pragma unroll
            for (int mi = 0; mi < 4; mi++) {
                int m = wm * 64 + mi * 16 + g;
                if constexpr (LA == 0) {
                    af[mi][0] = sa[(m)     * 20 + ks + t];
                    af[mi][1] = sa[(m + 8) * 20 + ks + t];
                    af[mi][2] = sa[(m)     * 20 + ks + t + 4];
                    af[mi][3] = sa[(m + 8) * 20 + ks + t + 4];
                } else {
                    af[mi][0] = sa[(ks + t)     * 136 + m];
                    af[mi][1] = sa[(ks + t)     * 136 + m + 8];
                    af[mi][2] = sa[(ks + t + 4) * 136 + m];
                    af[mi][3] = sa[(ks + t + 4) * 136 + m + 8];
                }
            }
#pragma unroll
            for (int ni = 0; ni < 4; ni++) {
                int n = wn * 32 + ni * 8 + g;
                if constexpr (LB == 1) {
                    bf[ni][0] = sb[n * 20 + ks + t];
                    bf[ni][1] = sb[n * 20 + ks + t + 4];
                } else {
                    bf[ni][0] = sb[(ks + t)     * 136 + n];
                    bf[ni][1] = sb[(ks + t + 4) * 136 + n];
                }
            }
#pragma unroll
            for (int mi = 0; mi < 4; mi++)
#pragma unroll
                for (int ni = 0; ni < 4; ni++)
                    mma8(acc[mi][ni], af[mi], bf[ni]);
        }
        __syncthreads();
        if (kt + 1 < ktiles) { sstore(); __syncthreads(); }
    }

    // epilogue + writeback (thread owns rows {g, g+8} of each 16-row tile, cols {2t, 2t+1})
#pragma unroll
    for (int mi = 0; mi < 4; mi++) {
        int mr = m0 + wm * 64 + mi * 16 + g;
        float b0 = 0.f, b1 = 0.f;
        if constexpr (EPI == 1) { b0 = auxp[mr]; b1 = auxp[mr + 8]; }
#pragma unroll
        for (int ni = 0; ni < 4; ni++) {
            int n = n0 + wn * 32 + ni * 8 + 2 * t;
            float s0 = 1.f, s1 = 1.f;
            if constexpr (EPI == 2) { s0 = auxp[n]; s1 = auxp[n + 1]; }
            float2 v0, v1;
            v0.x = acc[mi][ni][0] * s0 + b0;  v0.y = acc[mi][ni][1] * s1 + b0;
            v1.x = acc[mi][ni][2] * s0 + b1;  v1.y = acc[mi][ni][3] * s1 + b1;
            *(float2*)(C + (long long)mr * ldc + n)       = v0;
            *(float2*)(C + (long long)(mr + 8) * ldc + n) = v1;
        }
    }
}

// ---------------- E = exp(scores) in place + row sums ----------------
// Block = 8 full rows of one batch. Row reduce in shared, write 1/rowsum.
__global__ void e_sum_kernel()
{
    int blk = blockIdx.x;            // 0..2047
    int b   = blk >> 7;
    int r0  = (blk & 127) * 8;
    int tid = threadIdx.x;
    float* base = g_sc + ((long long)b << 20) + (long long)r0 * N_;

    __shared__ float srow[8][256];
#pragma unroll
    for (int r = 0; r < 8; r++) {
        float4* p = (float4*)(base + (long long)r * N_) + tid;
        float4 v = *p;
        v.x = __expf(v.x); v.y = __expf(v.y); v.z = __expf(v.z); v.w = __expf(v.w);
        *p = v;
        srow[r][tid] = v.x + v.y + v.z + v.w;
    }
    __syncthreads();
    int w = tid >> 5, lane = tid & 31;
    float s = 0.f;
#pragma unroll
    for (int i = 0; i < 8; i++) s += srow[w][lane + 32 * i];
#pragma unroll
    for (int off = 16; off; off >>= 1) s += __shfl_xor_sync(0xffffffffu, s, off);
    if (lane == 0) g_rsum[(b << 10) + r0 + w] = 1.f / s;
}

// 1/colsum: one thread per (b, m); coalesced strided reads of E.
__global__ void col_sum_kernel()
{
    int col = blockIdx.x * blockDim.x + threadIdx.x;   // 0..16383
    int b = col >> 10, m = col & (N_ - 1);
    const float* p = g_sc + ((long long)b << 20) + m;
    float s = 0.f;
#pragma unroll 8
    for (int n = 0; n < N_; n++) s += p[(long long)n << 10];
    g_csum[col] = 1.f / s;
}

// ---------------- batchnorm ----------------
__global__ void bn_stats_kernel(const float* __restrict__ z)
{
    int ch = blockIdx.x;                 // 0..1023
    int s = ch >> 9, c = ch & (C_ - 1);
    const float* base = z + ((long long)s * B_ * C_ + c) * N_;
    float sum = 0.f, sq = 0.f;
    for (int i = threadIdx.x; i < B_ * N_; i += 256) {
        int b = i >> 10, n = i & (N_ - 1);
        float x = base[((long long)b * C_) * (long long)N_ + n];
        sum += x; sq += x * x;
    }
    __shared__ float ssum[256], ssq[256];
    int tid = threadIdx.x;
    ssum[tid] = sum; ssq[tid] = sq;
    __syncthreads();
    for (int o = 128; o > 0; o >>= 1) {
        if (tid < o) { ssum[tid] += ssum[tid + o]; ssq[tid] += ssq[tid + o]; }
        __syncthreads();
    }
    if (tid == 0) {
        const float inv = 1.f / (float)(B_ * N_);
        float mean = ssum[0] * inv;
        float var  = ssq[0] * inv - mean * mean;
        g_mean[ch] = mean;
        g_rstd[ch] = rsqrtf(var + EPS_);
    }
}

__global__ void finalize_kernel(float* __restrict__ out,
                                const float* __restrict__ rgb, const float* __restrict__ flow,
                                const float* __restrict__ gr,  const float* __restrict__ br,
                                const float* __restrict__ gf,  const float* __restrict__ bf)
{
    const long long half4  = ((long long)B_ * C_ * N_) >> 2;
    const long long total4 = half4 * 2;
    const long long stride = (long long)gridDim.x * blockDim.x;
    for (long long i = (long long)blockIdx.x * blockDim.x + threadIdx.x; i < total4; i += stride) {
        int s = (i >= half4);
        long long r4 = i - (long long)s * half4;
        long long e  = r4 << 2;
        int c = (int)((e >> 10) & (C_ - 1));
        float mean = g_mean[(s << 9) + c];
        float a    = g_rstd[(s << 9) + c] * (s ? gf[c] : gr[c]);
        float be   = (s ? bf[c] : br[c]);
        float4 res = *((const float4*)(s ? flow : rgb) + r4);
        float4 z   = *((float4*)out + i);
        z.x = (z.x - mean) * a + be + res.x;
        z.y = (z.y - mean) * a + be + res.y;
        z.z = (z.z - mean) * a + be + res.z;
        z.w = (z.w - mean) * a + be + res.w;
        *((float4*)out + i) = z;
    }
}

// ---------------- launcher ----------------
extern "C" void kernel_launch(void* const* d_in, const int* in_sizes, int n_in,
                              void* d_out, int out_size)
{
    const float* rgb        = (const float*)d_in[0];
    const float* flow       = (const float*)d_in[1];
    const float* wg_rgb     = (const float*)d_in[2];
    const float* bg_rgb     = (const float*)d_in[3];
    const float* wg_flow    = (const float*)d_in[4];
    const float* bg_flow    = (const float*)d_in[5];
    const float* ww_rgb     = (const float*)d_in[6];
    const float* bw_rgb     = (const float*)d_in[7];
    const float* gamma_rgb  = (const float*)d_in[8];
    const float* beta_rgb   = (const float*)d_in[9];
    const float* ww_flow    = (const float*)d_in[10];
    const float* bw_flow    = (const float*)d_in[11];
    const float* gamma_flow = (const float*)d_in[12];
    const float* beta_flow  = (const float*)d_in[13];
    float* out = (float*)d_out;

    static float *re = nullptr, *fe, *sc, *yr, *yf, *rsum, *csum;
    if (!re) {
        cudaGetSymbolAddress((void**)&re,   g_re);
        cudaGetSymbolAddress((void**)&fe,   g_fe);
        cudaGetSymbolAddress((void**)&sc,   g_sc);
        cudaGetSymbolAddress((void**)&yr,   g_yr);
        cudaGetSymbolAddress((void**)&yf,   g_yf);
        cudaGetSymbolAddress((void**)&rsum, g_rsum);
        cudaGetSymbolAddress((void**)&csum, g_csum);
    }

    const long long sEmb = (long long)CI_ * N_;
    const long long sIn  = (long long)C_  * N_;
    const long long sSc  = (long long)N_  * N_;
    dim3 blk(256);

    // 1) embeddings: re = wg_rgb @ rgb + bg ; fe = wg_flow @ flow + bg
    mma_gemm<0, 0, 1><<<dim3(8, 2, B_), blk>>>(wg_rgb, rgb, re, bg_rgb,
        CI_, N_, C_, C_, N_, N_, 0, sIn, sEmb, 0);
    mma_gemm<0, 0, 1><<<dim3(8, 2, B_), blk>>>(wg_flow, flow, fe, bg_flow,
        CI_, N_, C_, C_, N_, N_, 0, sIn, sEmb, 0);

    // 2) scores[n,m] = sum_i re[i,n] * fe[i,m]   (A k-major, B row-major)
    mma_gemm<1, 0, 0><<<dim3(8, 8, B_), blk>>>(re, fe, sc, nullptr,
        N_, N_, CI_, N_, N_, N_, sEmb, sEmb, sSc, 0);

    // 3) E = exp(scores) in place; 1/rowsum and 1/colsum
    e_sum_kernel<<<B_ * 128, 256>>>();
    col_sum_kernel<<<64, 256>>>();

    // 4) attention applies with softmax normalization folded into epilogue:
    //    rgb_y[ci,n] = (sum_m fe[ci,m] E[n,m]) * rsum[n]   (B is [N][K] -> LB=1)
    //    flow_y[ci,m] = (sum_n re[ci,n] E[n,m]) * csum[m]  (B is [K][N] -> LB=0)
    mma_gemm<0, 1, 2><<<dim3(8, 2, B_), blk>>>(fe, sc, yr, rsum,
        CI_, N_, N_, N_, N_, N_, sEmb, sSc, sEmb, N_);
    mma_gemm<0, 0, 2><<<dim3(8, 2, B_), blk>>>(re, sc, yf, csum,
        CI_, N_, N_, N_, N_, N_, sEmb, sSc, sEmb, N_);

    // 5) output convs (pre-BN z straight into d_out)
    mma_gemm<0, 0, 1><<<dim3(8, 4, B_), blk>>>(ww_rgb, yr, out, bw_rgb,
        C_, N_, CI_, CI_, N_, N_, 0, sEmb, sIn, 0);
    mma_gemm<0, 0, 1><<<dim3(8, 4, B_), blk>>>(ww_flow, yf, out + (long long)B_ * C_ * N_, bw_flow,
        C_, N_, CI_, CI_, N_, N_, 0, sEmb, sIn, 0);

    // 6) BN stats + normalize + residual
    bn_stats_kernel<<<2 * C_, 256>>>(out);
    finalize_kernel<<<1184, 256>>>(out, rgb, flow, gamma_rgb, beta_rgb, gamma_flow, beta_flow);
}